// round 16
// baseline (speedup 1.0000x reference)
#include <cuda_runtime.h>
#include <cuda_fp16.h>

// Problem constants (fixed shapes)
#define N_NODES 65536
#define N_EDGES 1048576
#define C_IN    22
#define C_PAD   24
#define H_DIM   64
#define B_SZ    16
#define L_SEQ   4096
#define T_CH    32
#define KW      3
#define L1_OUT  4098
#define L2_OUT  4100
#define NCLS    3
#define EPSF    1e-5

#define CNT_SHIFT 42
#define FIX_SCALE 16777216.0f   // 2^24

typedef unsigned long long ull;

__device__ __forceinline__ ull fma2(ull a, ull b, ull c) {
    ull d;
    asm("fma.rn.f32x2 %0, %1, %2, %3;" : "=l"(d) : "l"(a), "l"(b), "l"(c));
    return d;
}
__device__ __forceinline__ ull pack2(float x, float y) {
    union { float2 f; ull u; } cv; cv.f = make_float2(x, y); return cv.u;
}
__device__ __forceinline__ float2 unpack2(ull u) {
    union { ull u; float2 f; } cv; cv.u = u; return cv.f;
}

// ---------------- scratch ----------------
__device__ ull            g_pack[N_NODES]; // count<<42 | fixpoint(deg_extra, 2^24)
__device__ unsigned short g_rank[N_EDGES]; // rank of edge within its dst segment
__device__ __half  g_hx[N_NODES * C_PAD];  // fp16 x, padded to 24/row
__device__ float   g_aggx[N_NODES * C_IN];
__device__ __half  g_hbuf[N_NODES * H_DIM];   // pre-agg layer2 (fp16)
__device__ __half  g_h2buf[N_NODES * H_DIM];  // h2 activated (fp16)
__device__ float   g_dinv[N_NODES];
__device__ int     g_off[N_NODES + 1];
__device__ int     g_bsum[256];
__device__ int2    g_edge[N_EDGES];        // (src, dinv[src]*ew as bits), dst-sorted
__device__ __half  g_y1[B_SZ * T_CH * L1_OUT];
__device__ __half  g_y2[B_SZ * T_CH * L2_OUT];
__device__ double  g_dstats[128];
__device__ float   g_pool[B_SZ * T_CH];
__device__ int     g_done;
__device__ int     g_barrier;

// ---------------- fused histogram + x->fp16 conversion ----------------------
__global__ void k_deg_hist(const int* __restrict__ ei, const float* __restrict__ ew,
                           const float* __restrict__ x) {
    int e = blockIdx.x * blockDim.x + threadIdx.x;
    if (e == 0) g_barrier = 0;
    if (e < N_EDGES) {
        int c = ei[N_EDGES + e];
        ull fx = (ull)(ew[e] * FIX_SCALE + 0.5f);
        ull old = atomicAdd(&g_pack[c], (1ULL << CNT_SHIFT) | fx);
        g_rank[e] = (unsigned short)(old >> CNT_SHIFT);
    }
    for (int i = e; i < N_NODES * C_IN; i += N_EDGES) {
        int r = i / C_IN, c = i - r * C_IN;
        g_hx[r * C_PAD + c] = __float2half(x[i]);
    }
}

// ---------------- fused scan + place ----------------------------------------
__device__ __forceinline__ void grid_barrier(int target) {
    __syncthreads();
    if (threadIdx.x == 0) {
        __threadfence();
        atomicAdd(&g_barrier, 1);
        while (*(volatile int*)&g_barrier < target) {}
    }
    __syncthreads();
}

__global__ void k_scanplace(const int* __restrict__ ei, const float* __restrict__ ew) {
    __shared__ int s[256];
    int tid = threadIdx.x;
    int i = blockIdx.x * 256 + tid;
    if (blockIdx.x == 0) {
        if (tid < 128) g_dstats[tid] = 0.0;
        if (tid == 128) g_done = 0;
    }
    ull pk = g_pack[i];
    int v = (int)(pk >> CNT_SHIFT);
    float deg = 1.0f + (float)(pk & ((1ULL << CNT_SHIFT) - 1)) * (1.0f / FIX_SCALE);
    g_dinv[i] = rsqrtf(deg);
    s[tid] = v;
    __syncthreads();
    for (int st = 1; st < 256; st <<= 1) {
        int a = (tid >= st) ? s[tid - st] : 0;
        __syncthreads();
        s[tid] += a;
        __syncthreads();
    }
    int local_excl = s[tid] - v;
    if (tid == 255) g_bsum[blockIdx.x] = s[255];
    grid_barrier(256);

    s[tid] = (tid < (int)blockIdx.x) ? g_bsum[tid] : 0;
    __syncthreads();
    for (int st = 128; st > 0; st >>= 1) {
        if (tid < st) s[tid] += s[tid + st];
        __syncthreads();
    }
    g_off[i] = local_excl + s[0];
    if (i == 0) g_off[N_NODES] = N_EDGES;
    grid_barrier(512);

    int base = blockIdx.x * 256 + tid;
#pragma unroll 4
    for (int k = 0; k < 16; k++) {
        int e = base + k * 65536;
        int r = ei[e];
        int c = ei[N_EDGES + e];
        float w = g_dinv[r] * ew[e];
        int pos = g_off[c] + (int)g_rank[e];
        g_edge[pos] = make_int2(r, __float_as_int(w));
    }
}

// ---------------- layer-1 aggregation on fp16 x ----------------
__global__ void k_gather22() {
    int warp = (blockIdx.x * blockDim.x + threadIdx.x) >> 5;
    int lane = threadIdx.x & 31;
    if (warp >= N_NODES) return;
    bool act = lane < 11;
    int beg = g_off[warp], end = g_off[warp + 1];
    const __half2* __restrict__ src = (const __half2*)g_hx;  // row stride 12
    float ax = 0.f, ay = 0.f;
    int e = beg;
    for (; e + 3 < end; e += 4) {
        int2 e0 = g_edge[e];
        int2 e1 = g_edge[e + 1];
        int2 e2 = g_edge[e + 2];
        int2 e3 = g_edge[e + 3];
        if (act) {
            float2 v0 = __half22float2(src[e0.x * 12 + lane]);
            float2 v1 = __half22float2(src[e1.x * 12 + lane]);
            float2 v2 = __half22float2(src[e2.x * 12 + lane]);
            float2 v3 = __half22float2(src[e3.x * 12 + lane]);
            float w0 = __int_as_float(e0.y);
            float w1 = __int_as_float(e1.y);
            float w2 = __int_as_float(e2.y);
            float w3 = __int_as_float(e3.y);
            ax += w0 * v0.x + w1 * v1.x + w2 * v2.x + w3 * v3.x;
            ay += w0 * v0.y + w1 * v1.y + w2 * v2.y + w3 * v3.y;
        }
    }
    for (; e < end; e++) {
        int2 e0 = g_edge[e];
        if (act) {
            float2 v0 = __half22float2(src[e0.x * 12 + lane]);
            float w0 = __int_as_float(e0.y);
            ax += w0 * v0.x;
            ay += w0 * v0.y;
        }
    }
    float d = g_dinv[warp];
    if (act) {
        float2 sv = __half22float2(src[warp * 12 + lane]);
        ax = d * (ax + d * sv.x);
        ay = d * (ay + d * sv.y);
        *(float2*)&g_aggx[(size_t)warp * C_IN + 2 * lane] = make_float2(ax, ay);
    }
}

// ---------------- fused GEMM: relu(aggx@W1+b1) @ W2 -> hbuf fp16 ------------
// h1 stored DUPLICATED in smem (sh2[row][2c]=(v,v)) so phase-B activation
// operand is a single natural LDS.64 — no packing MOVs in the hot loop.
// Dynamic smem layout (floats):
//   sW1  [0, 1408)         sW2 [1408, 5504)
//   sx   [5504, 6912)      sh2 [6912, 15360)  (64 rows x 132)
#define G12_SMEM_FLOATS 15360
__global__ void k_gemm12(const float* __restrict__ W1, const float* __restrict__ b1,
                         const float* __restrict__ W2) {
    extern __shared__ __align__(16) float smem[];
    float* sW1 = smem;
    float* sW2 = smem + 1408;
    float* sx  = smem + 5504;
    float* sh2 = smem + 6912;
    int t = threadIdx.x;
    int n0 = blockIdx.x * 64;
    for (int i = t; i < C_IN * H_DIM; i += 256) sW1[i] = W1[i];
    for (int i = t; i < H_DIM * H_DIM; i += 256) sW2[i] = W2[i];
    for (int i = t; i < 64 * C_IN; i += 256) sx[i] = g_aggx[n0 * C_IN + i];
    __syncthreads();

    int tf = t & 15, tn = t >> 4;
    int f4 = tf * 4;

    // phase A: h1 = relu(aggx @ W1 + b1) -> sh2 (duplicated pairs)
    {
        float acc[4][4];
        float4 bv = *(const float4*)&b1[f4];
#pragma unroll
        for (int j = 0; j < 4; j++) {
            acc[j][0] = bv.x; acc[j][1] = bv.y; acc[j][2] = bv.z; acc[j][3] = bv.w;
        }
#pragma unroll
        for (int c = 0; c < C_IN; c++) {
            float4 wv = *(const float4*)&sW1[c * H_DIM + f4];
#pragma unroll
            for (int j = 0; j < 4; j++) {
                float hv = sx[(tn * 4 + j) * C_IN + c];
                acc[j][0] += hv * wv.x; acc[j][1] += hv * wv.y;
                acc[j][2] += hv * wv.z; acc[j][3] += hv * wv.w;
            }
        }
#pragma unroll
        for (int j = 0; j < 4; j++) {
            int row = tn * 4 + j;
#pragma unroll
            for (int q = 0; q < 4; q++) {
                float v = fmaxf(acc[j][q], 0.f);
                *(float2*)&sh2[row * 132 + 2 * (f4 + q)] = make_float2(v, v);
            }
        }
    }
    __syncthreads();

    // phase B: h2pre = h1 @ W2 -> hbuf (fp16); pure LDS.64 + fma2
    {
        ull A[4][2];
#pragma unroll
        for (int j = 0; j < 4; j++) { A[j][0] = 0; A[j][1] = 0; }
#pragma unroll 8
        for (int c = 0; c < H_DIM; c++) {
            ull wp0 = *(const ull*)&sW2[c * H_DIM + f4];
            ull wp1 = *(const ull*)&sW2[c * H_DIM + f4 + 2];
#pragma unroll
            for (int j = 0; j < 4; j++) {
                ull hv = *(const ull*)&sh2[(tn * 4 + j) * 132 + 2 * c];
                A[j][0] = fma2(hv, wp0, A[j][0]);
                A[j][1] = fma2(hv, wp1, A[j][1]);
            }
        }
#pragma unroll
        for (int j = 0; j < 4; j++) {
            int n = n0 + tn * 4 + j;
            float2 a0 = unpack2(A[j][0]), a1 = unpack2(A[j][1]);
            __half2* p = (__half2*)&g_hbuf[n * H_DIM + f4];
            p[0] = __floats2half2_rn(a0.x, a0.y);
            p[1] = __floats2half2_rn(a1.x, a1.y);
        }
    }
}

// ---------------- layer-2 CSR gather + bias + relu -> h2buf (fp16) ----------
__global__ void k_gather64(const float* __restrict__ bias) {
    int warp = (blockIdx.x * blockDim.x + threadIdx.x) >> 5;
    int lane = threadIdx.x & 31;
    if (warp >= N_NODES) return;
    int beg = g_off[warp], end = g_off[warp + 1];
    const __half2* __restrict__ src = (const __half2*)g_hbuf;
    float ax = 0.f, ay = 0.f;
    int e = beg;
    for (; e + 3 < end; e += 4) {
        int2 e0 = g_edge[e];
        int2 e1 = g_edge[e + 1];
        int2 e2 = g_edge[e + 2];
        int2 e3 = g_edge[e + 3];
        float2 v0 = __half22float2(src[(size_t)e0.x * 32 + lane]);
        float2 v1 = __half22float2(src[(size_t)e1.x * 32 + lane]);
        float2 v2 = __half22float2(src[(size_t)e2.x * 32 + lane]);
        float2 v3 = __half22float2(src[(size_t)e3.x * 32 + lane]);
        float w0 = __int_as_float(e0.y);
        float w1 = __int_as_float(e1.y);
        float w2 = __int_as_float(e2.y);
        float w3 = __int_as_float(e3.y);
        ax += w0 * v0.x + w1 * v1.x + w2 * v2.x + w3 * v3.x;
        ay += w0 * v0.y + w1 * v1.y + w2 * v2.y + w3 * v3.y;
    }
    for (; e < end; e++) {
        int2 e0 = g_edge[e];
        float2 v0 = __half22float2(src[(size_t)e0.x * 32 + lane]);
        float w0 = __int_as_float(e0.y);
        ax += w0 * v0.x;
        ay += w0 * v0.y;
    }
    float d = g_dinv[warp];
    float2 s = __half22float2(src[(size_t)warp * 32 + lane]);
    ax = d * (ax + d * s.x) + bias[lane * 2];
    ay = d * (ay + d * s.y) + bias[lane * 2 + 1];
    ((__half2*)g_h2buf)[(size_t)warp * 32 + lane] =
        __floats2half2_rn(fmaxf(ax, 0.f), fmaxf(ay, 0.f));
}

// ---------------- conv1: fp16 in/out, f32x2 math, fused BN1 stats -----------
__global__ void k_conv1(const float* __restrict__ w, const float* __restrict__ bias) {
    __shared__ __align__(16) float sw[H_DIM * KW * 36];   // sw[(i*3+k)*36 + o]
    __shared__ float sx[130 * 65];
    __shared__ float s_sum[T_CH], s_sq[T_CH];
    int b = blockIdx.y;
    int t0 = blockIdx.x * 128;
    int t = threadIdx.x;
    if (t < T_CH) { s_sum[t] = 0.f; s_sq[t] = 0.f; }
    for (int j = t; j < T_CH * H_DIM * KW; j += 128) {
        int o = j / (H_DIM * KW), ik = j % (H_DIM * KW);
        sw[ik * 36 + o] = w[j];
    }
    const __half2* __restrict__ hsrc = (const __half2*)g_h2buf;
    for (int j = t; j < 130 * 32; j += 128) {
        int row = j >> 5, cp = j & 31;
        int l = t0 + row - 2;
        float2 v = make_float2(0.f, 0.f);
        if (l >= 0 && l < L_SEQ)
            v = __half22float2(hsrc[((size_t)((b << 12) + l)) * 32 + cp]);
        sx[row * 65 + 2 * cp] = v.x;
        sx[row * 65 + 2 * cp + 1] = v.y;
    }
    __syncthreads();
    int to = t & 7, tq = t >> 3;
    int o4 = to * 4;
    ull A[8][2];
    ull bi0 = pack2(bias[o4], bias[o4 + 1]);
    ull bi1 = pack2(bias[o4 + 2], bias[o4 + 3]);
#pragma unroll
    for (int j = 0; j < 8; j++) { A[j][0] = bi0; A[j][1] = bi1; }
#pragma unroll 4
    for (int i = 0; i < H_DIM; i++) {
        ull xd[10];
#pragma unroll
        for (int r = 0; r < 10; r++) {
            float v = sx[(8 * tq + r) * 65 + i];
            xd[r] = pack2(v, v);
        }
#pragma unroll
        for (int k = 0; k < KW; k++) {
            ulonglong2 wv = *(const ulonglong2*)&sw[(i * 3 + k) * 36 + o4];
#pragma unroll
            for (int j = 0; j < 8; j++) {
                A[j][0] = fma2(xd[j + k], wv.x, A[j][0]);
                A[j][1] = fma2(xd[j + k], wv.y, A[j][1]);
            }
        }
    }
    float acc[8][4];
#pragma unroll
    for (int j = 0; j < 8; j++) {
        float2 a0 = unpack2(A[j][0]), a1 = unpack2(A[j][1]);
        acc[j][0] = a0.x; acc[j][1] = a0.y; acc[j][2] = a1.x; acc[j][3] = a1.y;
    }
    int tb = t0 + 8 * tq;
    float cs[4] = {0.f, 0.f, 0.f, 0.f}, cq[4] = {0.f, 0.f, 0.f, 0.f};
    if (tb + 7 < L1_OUT) {
#pragma unroll
        for (int c = 0; c < 4; c++) {
            __half* p = &g_y1[(b * T_CH + o4 + c) * L1_OUT + tb];
#pragma unroll
            for (int j = 0; j < 4; j++)
                ((__half2*)p)[j] = __floats2half2_rn(acc[2 * j][c], acc[2 * j + 1][c]);
#pragma unroll
            for (int j = 0; j < 8; j++) { cs[c] += acc[j][c]; cq[c] += acc[j][c] * acc[j][c]; }
        }
    } else {
#pragma unroll
        for (int c = 0; c < 4; c++) {
            __half* p = &g_y1[(b * T_CH + o4 + c) * L1_OUT + tb];
#pragma unroll
            for (int j = 0; j < 8; j++)
                if (tb + j < L1_OUT) {
                    p[j] = __float2half(acc[j][c]);
                    cs[c] += acc[j][c]; cq[c] += acc[j][c] * acc[j][c];
                }
        }
    }
#pragma unroll
    for (int c = 0; c < 4; c++) {
        atomicAdd(&s_sum[o4 + c], cs[c]);
        atomicAdd(&s_sq[o4 + c], cq[c]);
    }
    __syncthreads();
    if (t < T_CH) {
        atomicAdd(&g_dstats[t], (double)s_sum[t]);
        atomicAdd(&g_dstats[32 + t], (double)s_sq[t]);
    }
}

// ---------------- conv2: BN1 inline, fp16 in/out, fused BN2 stats -----------
__global__ void k_conv2(const float* __restrict__ w, const float* __restrict__ bias,
                        const float* __restrict__ g1, const float* __restrict__ be1) {
    __shared__ __align__(16) float sw[T_CH * KW * 36];
    __shared__ float sx[130 * 33];
    __shared__ float s_ga[T_CH], s_bb[T_CH];
    __shared__ float s_sum[T_CH], s_sq[T_CH];
    int b = blockIdx.y;
    int t0 = blockIdx.x * 128;
    int t = threadIdx.x;
    if (t < T_CH) {
        double n = (double)B_SZ * L1_OUT;
        double m = g_dstats[t] / n;
        double var = g_dstats[32 + t] / n - m * m;
        float rs = (float)rsqrt(var + EPSF);
        float ga = g1[t] * rs;
        s_ga[t] = ga;
        s_bb[t] = be1[t] - (float)m * ga;
        s_sum[t] = 0.f; s_sq[t] = 0.f;
    }
    for (int j = t; j < T_CH * T_CH * KW; j += 128) {
        int o = j / (T_CH * KW), ik = j % (T_CH * KW);
        sw[ik * 36 + o] = w[j];
    }
    __syncthreads();
    for (int j = t; j < 32 * 130; j += 128) {
        int i = j / 130, row = j % 130;
        int l = t0 + row - 2;
        float v = 0.f;
        if (l >= 0 && l < L1_OUT)
            v = fmaxf(__half2float(g_y1[(b * T_CH + i) * L1_OUT + l]) * s_ga[i] + s_bb[i], 0.f);
        sx[row * 33 + i] = v;
    }
    __syncthreads();
    int to = t & 7, tq = t >> 3;
    int o4 = to * 4;
    ull A[8][2];
    ull bi0 = pack2(bias[o4], bias[o4 + 1]);
    ull bi1 = pack2(bias[o4 + 2], bias[o4 + 3]);
#pragma unroll
    for (int j = 0; j < 8; j++) { A[j][0] = bi0; A[j][1] = bi1; }
#pragma unroll 4
    for (int i = 0; i < T_CH; i++) {
        ull xd[10];
#pragma unroll
        for (int r = 0; r < 10; r++) {
            float v = sx[(8 * tq + r) * 33 + i];
            xd[r] = pack2(v, v);
        }
#pragma unroll
        for (int k = 0; k < KW; k++) {
            ulonglong2 wv = *(const ulonglong2*)&sw[(i * 3 + k) * 36 + o4];
#pragma unroll
            for (int j = 0; j < 8; j++) {
                A[j][0] = fma2(xd[j + k], wv.x, A[j][0]);
                A[j][1] = fma2(xd[j + k], wv.y, A[j][1]);
            }
        }
    }
    float acc[8][4];
#pragma unroll
    for (int j = 0; j < 8; j++) {
        float2 a0 = unpack2(A[j][0]), a1 = unpack2(A[j][1]);
        acc[j][0] = a0.x; acc[j][1] = a0.y; acc[j][2] = a1.x; acc[j][3] = a1.y;
    }
    int tb = t0 + 8 * tq;
    float cs[4] = {0.f, 0.f, 0.f, 0.f}, cq[4] = {0.f, 0.f, 0.f, 0.f};
    if (tb + 7 < L2_OUT) {
#pragma unroll
        for (int c = 0; c < 4; c++) {
            __half* p = &g_y2[(b * T_CH + o4 + c) * L2_OUT + tb];
#pragma unroll
            for (int j = 0; j < 4; j++)
                ((__half2*)p)[j] = __floats2half2_rn(acc[2 * j][c], acc[2 * j + 1][c]);
#pragma unroll
            for (int j = 0; j < 8; j++) { cs[c] += acc[j][c]; cq[c] += acc[j][c] * acc[j][c]; }
        }
    } else {
#pragma unroll
        for (int c = 0; c < 4; c++) {
            __half* p = &g_y2[(b * T_CH + o4 + c) * L2_OUT + tb];
#pragma unroll
            for (int j = 0; j < 8; j++)
                if (tb + j < L2_OUT) {
                    p[j] = __float2half(acc[j][c]);
                    cs[c] += acc[j][c]; cq[c] += acc[j][c] * acc[j][c];
                }
        }
    }
#pragma unroll
    for (int c = 0; c < 4; c++) {
        atomicAdd(&s_sum[o4 + c], cs[c]);
        atomicAdd(&s_sq[o4 + c], cq[c]);
    }
    __syncthreads();
    if (t < T_CH) {
        atomicAdd(&g_dstats[64 + t], (double)s_sum[t]);
        atomicAdd(&g_dstats[96 + t], (double)s_sq[t]);
    }
}

// ---------------- BN2 + relu + mean pool, last block runs FC head ----------
__global__ void k_pool_fc(const float* __restrict__ g2, const float* __restrict__ be2,
                          const float* __restrict__ fc1_w, const float* __restrict__ fc1_b,
                          const float* __restrict__ fc2_w, const float* __restrict__ fc2_b,
                          float* __restrict__ out) {
    int b = blockIdx.x >> 5, o = blockIdx.x & 31;
    double n = (double)B_SZ * L2_OUT;
    double md = g_dstats[64 + o] / n;
    double var = g_dstats[96 + o] / n - md * md;
    float rs = (float)rsqrt(var + EPSF);
    float ga = g2[o] * rs;
    float bb = be2[o] - (float)md * ga;
    const __half* y = g_y2 + (b * T_CH + o) * L2_OUT;
    float s = 0.f;
    for (int i = threadIdx.x; i < L2_OUT; i += 256)
        s += fmaxf(__half2float(y[i]) * ga + bb, 0.f);
    __shared__ float sm[256];
    sm[threadIdx.x] = s;
    __syncthreads();
    for (int st = 128; st > 0; st >>= 1) {
        if (threadIdx.x < st) sm[threadIdx.x] += sm[threadIdx.x + st];
        __syncthreads();
    }
    __shared__ bool last;
    if (threadIdx.x == 0) {
        g_pool[b * T_CH + o] = sm[0] / (float)L2_OUT;
        __threadfence();
        int d = atomicAdd(&g_done, 1);
        last = (d == B_SZ * T_CH - 1);
    }
    __syncthreads();
    if (!last) return;

    __threadfence();
    __shared__ float z[B_SZ * H_DIM];
    int t = threadIdx.x;
    for (int i = t; i < B_SZ * H_DIM; i += 256) {
        int bb2 = i >> 6, j = i & 63;
        float acc = fc1_b[j];
#pragma unroll
        for (int c = 0; c < T_CH; c++)
            acc += __ldcg(&g_pool[bb2 * T_CH + c]) * fc1_w[c * H_DIM + j];
        z[i] = fmaxf(acc, 0.f);
    }
    __syncthreads();
    for (int i = t; i < B_SZ * NCLS; i += 256) {
        int bb2 = i / NCLS, c = i % NCLS;
        float acc = fc2_b[c];
#pragma unroll
        for (int j = 0; j < H_DIM; j++) acc += z[bb2 * H_DIM + j] * fc2_w[j * NCLS + c];
        out[i] = acc;
    }
}

// ---------------- launcher ----------------
extern "C" void kernel_launch(void* const* d_in, const int* in_sizes, int n_in,
                              void* d_out, int out_size) {
    const float* x      = (const float*)d_in[0];
    const float* ew     = (const float*)d_in[1];
    const float* W1     = (const float*)d_in[2];
    const float* b1     = (const float*)d_in[3];
    const float* W2     = (const float*)d_in[4];
    const float* b2     = (const float*)d_in[5];
    const float* tc1_w  = (const float*)d_in[6];
    const float* tc1_b  = (const float*)d_in[7];
    const float* bn1_g  = (const float*)d_in[8];
    const float* bn1_b  = (const float*)d_in[9];
    const float* tc2_w  = (const float*)d_in[10];
    const float* tc2_b  = (const float*)d_in[11];
    const float* bn2_g  = (const float*)d_in[12];
    const float* bn2_b  = (const float*)d_in[13];
    const float* fc1_w  = (const float*)d_in[14];
    const float* fc1_b  = (const float*)d_in[15];
    const float* fc2_w  = (const float*)d_in[16];
    const float* fc2_b  = (const float*)d_in[17];
    const int*   ei     = (const int*)d_in[18];
    float* out = (float*)d_out;

    void* pack_ptr = nullptr;
    cudaGetSymbolAddress(&pack_ptr, g_pack);
    cudaMemsetAsync(pack_ptr, 0, N_NODES * sizeof(ull));

    // allow >48KB dynamic smem for k_gemm12 (host-side attr, capture-safe)
    cudaFuncSetAttribute(k_gemm12, cudaFuncAttributeMaxDynamicSharedMemorySize,
                         G12_SMEM_FLOATS * sizeof(float));

    // CSR build: histogram (+ x->fp16 convert), then fused scan+place
    k_deg_hist<<<N_EDGES / 256, 256>>>(ei, ew, x);
    k_scanplace<<<256, 256>>>(ei, ew);

    // GCN layer 1 + layer-2 transform fused: gather, then gemm1+gemm2
    k_gather22<<<N_NODES * 32 / 256, 256>>>();
    k_gemm12<<<N_NODES / 64, 256, G12_SMEM_FLOATS * sizeof(float)>>>(W1, b1, W2);

    // GCN layer 2 aggregation (+bias+relu, fp16 out)
    k_gather64<<<N_NODES * 32 / 256, 256>>>(b2);

    // temporal convs with fused BN stats (fp16 activations, fp32 math)
    k_conv1<<<dim3((L1_OUT + 127) / 128, B_SZ), 128>>>(tc1_w, tc1_b);
    k_conv2<<<dim3((L2_OUT + 127) / 128, B_SZ), 128>>>(tc2_w, tc2_b, bn1_g, bn1_b);

    // BN2 + relu + pool + FC head (fused)
    k_pool_fc<<<B_SZ * T_CH, 256>>>(bn2_g, bn2_b, fc1_w, fc1_b, fc2_w, fc2_b, out);
}

// round 17
// speedup vs baseline: 1.0589x; 1.0589x over previous
#include <cuda_runtime.h>
#include <cuda_fp16.h>

// Problem constants (fixed shapes)
#define N_NODES 65536
#define N_EDGES 1048576
#define C_IN    22
#define C_PAD   24
#define H_DIM   64
#define B_SZ    16
#define L_SEQ   4096
#define T_CH    32
#define KW      3
#define L1_OUT  4098
#define L2_OUT  4100
#define NCLS    3
#define EPSF    1e-5

#define CNT_SHIFT 42
#define FIX_SCALE 16777216.0f   // 2^24

typedef unsigned long long ull;

__device__ __forceinline__ ull fma2(ull a, ull b, ull c) {
    ull d;
    asm("fma.rn.f32x2 %0, %1, %2, %3;" : "=l"(d) : "l"(a), "l"(b), "l"(c));
    return d;
}
__device__ __forceinline__ ull pack2(float x, float y) {
    union { float2 f; ull u; } cv; cv.f = make_float2(x, y); return cv.u;
}
__device__ __forceinline__ float2 unpack2(ull u) {
    union { ull u; float2 f; } cv; cv.u = u; return cv.f;
}

// ---------------- scratch ----------------
__device__ ull            g_pack[N_NODES]; // count<<42 | fixpoint(deg_extra, 2^24)
__device__ unsigned short g_rank[N_EDGES]; // rank of edge within its dst segment
__device__ __half  g_hx[N_NODES * C_PAD];  // fp16 x, padded to 24/row
__device__ float   g_aggx[N_NODES * C_IN];
__device__ __half  g_hbuf[N_NODES * H_DIM];   // pre-agg layer2 (fp16)
__device__ __half  g_h2buf[N_NODES * H_DIM];  // h2 activated (fp16)
__device__ float   g_dinv[N_NODES];
__device__ int     g_off[N_NODES + 1];
__device__ int     g_bsum[256];
__device__ int2    g_edge[N_EDGES];        // (src, dinv[src]*ew as bits), dst-sorted
__device__ __half  g_y1[B_SZ * T_CH * L1_OUT];
__device__ __half  g_y2[B_SZ * T_CH * L2_OUT];
__device__ double  g_dstats[128];
__device__ float   g_pool[B_SZ * T_CH];
__device__ int     g_done;
__device__ int     g_barrier;

// ---------------- fused histogram + x->fp16 conversion ----------------------
__global__ void k_deg_hist(const int* __restrict__ ei, const float* __restrict__ ew,
                           const float* __restrict__ x) {
    int e = blockIdx.x * blockDim.x + threadIdx.x;
    if (e == 0) g_barrier = 0;
    if (e < N_EDGES) {
        int c = ei[N_EDGES + e];
        ull fx = (ull)(ew[e] * FIX_SCALE + 0.5f);
        ull old = atomicAdd(&g_pack[c], (1ULL << CNT_SHIFT) | fx);
        g_rank[e] = (unsigned short)(old >> CNT_SHIFT);
    }
    for (int i = e; i < N_NODES * C_IN; i += N_EDGES) {
        int r = i / C_IN, c = i - r * C_IN;
        g_hx[r * C_PAD + c] = __float2half(x[i]);
    }
}

// ---------------- fused scan + place ----------------------------------------
__device__ __forceinline__ void grid_barrier(int target) {
    __syncthreads();
    if (threadIdx.x == 0) {
        __threadfence();
        atomicAdd(&g_barrier, 1);
        while (*(volatile int*)&g_barrier < target) {}
    }
    __syncthreads();
}

__global__ void k_scanplace(const int* __restrict__ ei, const float* __restrict__ ew) {
    __shared__ int s[256];
    int tid = threadIdx.x;
    int i = blockIdx.x * 256 + tid;
    if (blockIdx.x == 0) {
        if (tid < 128) g_dstats[tid] = 0.0;
        if (tid == 128) g_done = 0;
    }
    ull pk = g_pack[i];
    int v = (int)(pk >> CNT_SHIFT);
    float deg = 1.0f + (float)(pk & ((1ULL << CNT_SHIFT) - 1)) * (1.0f / FIX_SCALE);
    g_dinv[i] = rsqrtf(deg);
    s[tid] = v;
    __syncthreads();
    for (int st = 1; st < 256; st <<= 1) {
        int a = (tid >= st) ? s[tid - st] : 0;
        __syncthreads();
        s[tid] += a;
        __syncthreads();
    }
    int local_excl = s[tid] - v;
    if (tid == 255) g_bsum[blockIdx.x] = s[255];
    grid_barrier(256);

    s[tid] = (tid < (int)blockIdx.x) ? g_bsum[tid] : 0;
    __syncthreads();
    for (int st = 128; st > 0; st >>= 1) {
        if (tid < st) s[tid] += s[tid + st];
        __syncthreads();
    }
    g_off[i] = local_excl + s[0];
    if (i == 0) g_off[N_NODES] = N_EDGES;
    grid_barrier(512);

    int base = blockIdx.x * 256 + tid;
#pragma unroll 4
    for (int k = 0; k < 16; k++) {
        int e = base + k * 65536;
        int r = ei[e];
        int c = ei[N_EDGES + e];
        float w = g_dinv[r] * ew[e];
        int pos = g_off[c] + (int)g_rank[e];
        g_edge[pos] = make_int2(r, __float_as_int(w));
    }
}

// ---------------- layer-1 aggregation on fp16 x ----------------
__global__ void k_gather22() {
    int warp = (blockIdx.x * blockDim.x + threadIdx.x) >> 5;
    int lane = threadIdx.x & 31;
    if (warp >= N_NODES) return;
    bool act = lane < 11;
    int beg = g_off[warp], end = g_off[warp + 1];
    const __half2* __restrict__ src = (const __half2*)g_hx;  // row stride 12
    float ax = 0.f, ay = 0.f;
    int e = beg;
    for (; e + 3 < end; e += 4) {
        int2 e0 = g_edge[e];
        int2 e1 = g_edge[e + 1];
        int2 e2 = g_edge[e + 2];
        int2 e3 = g_edge[e + 3];
        if (act) {
            float2 v0 = __half22float2(src[e0.x * 12 + lane]);
            float2 v1 = __half22float2(src[e1.x * 12 + lane]);
            float2 v2 = __half22float2(src[e2.x * 12 + lane]);
            float2 v3 = __half22float2(src[e3.x * 12 + lane]);
            float w0 = __int_as_float(e0.y);
            float w1 = __int_as_float(e1.y);
            float w2 = __int_as_float(e2.y);
            float w3 = __int_as_float(e3.y);
            ax += w0 * v0.x + w1 * v1.x + w2 * v2.x + w3 * v3.x;
            ay += w0 * v0.y + w1 * v1.y + w2 * v2.y + w3 * v3.y;
        }
    }
    for (; e < end; e++) {
        int2 e0 = g_edge[e];
        if (act) {
            float2 v0 = __half22float2(src[e0.x * 12 + lane]);
            float w0 = __int_as_float(e0.y);
            ax += w0 * v0.x;
            ay += w0 * v0.y;
        }
    }
    float d = g_dinv[warp];
    if (act) {
        float2 sv = __half22float2(src[warp * 12 + lane]);
        ax = d * (ax + d * sv.x);
        ay = d * (ay + d * sv.y);
        *(float2*)&g_aggx[(size_t)warp * C_IN + 2 * lane] = make_float2(ax, ay);
    }
}

// ---------------- fused GEMM: relu(aggx@W1+b1) @ W2 -> hbuf fp16 ------------
// h1 never leaves shared memory; phase B uses f32x2 with register-dup.
__global__ void k_gemm12(const float* __restrict__ W1, const float* __restrict__ b1,
                         const float* __restrict__ W2) {
    __shared__ float sW1[C_IN * H_DIM];
    __shared__ __align__(16) float sW2[H_DIM * H_DIM];
    __shared__ float sx[64 * C_IN];
    __shared__ float sh[64 * 65];       // h1 tile, padded
    int t = threadIdx.x;
    int n0 = blockIdx.x * 64;
    for (int i = t; i < C_IN * H_DIM; i += 256) sW1[i] = W1[i];
    for (int i = t; i < H_DIM * H_DIM; i += 256) sW2[i] = W2[i];
    for (int i = t; i < 64 * C_IN; i += 256) sx[i] = g_aggx[n0 * C_IN + i];
    __syncthreads();

    int tf = t & 15, tn = t >> 4;
    int f4 = tf * 4;

    // phase A: h1 = relu(aggx @ W1 + b1) -> sh (scalar; K=22 small)
    {
        float acc[4][4];
        float4 bv = *(const float4*)&b1[f4];
#pragma unroll
        for (int j = 0; j < 4; j++) {
            acc[j][0] = bv.x; acc[j][1] = bv.y; acc[j][2] = bv.z; acc[j][3] = bv.w;
        }
#pragma unroll
        for (int c = 0; c < C_IN; c++) {
            float4 wv = *(const float4*)&sW1[c * H_DIM + f4];
#pragma unroll
            for (int j = 0; j < 4; j++) {
                float hv = sx[(tn * 4 + j) * C_IN + c];
                acc[j][0] += hv * wv.x; acc[j][1] += hv * wv.y;
                acc[j][2] += hv * wv.z; acc[j][3] += hv * wv.w;
            }
        }
#pragma unroll
        for (int j = 0; j < 4; j++) {
            int row = tn * 4 + j;
            sh[row * 65 + f4]     = fmaxf(acc[j][0], 0.f);
            sh[row * 65 + f4 + 1] = fmaxf(acc[j][1], 0.f);
            sh[row * 65 + f4 + 2] = fmaxf(acc[j][2], 0.f);
            sh[row * 65 + f4 + 3] = fmaxf(acc[j][3], 0.f);
        }
    }
    __syncthreads();

    // phase B: h2pre = h1 @ W2 -> hbuf (fp16), f32x2 register-dup
    {
        ull A[4][2];
#pragma unroll
        for (int j = 0; j < 4; j++) { A[j][0] = 0; A[j][1] = 0; }
#pragma unroll 8
        for (int c = 0; c < H_DIM; c++) {
            ull wp0 = *(const ull*)&sW2[c * H_DIM + f4];
            ull wp1 = *(const ull*)&sW2[c * H_DIM + f4 + 2];
#pragma unroll
            for (int j = 0; j < 4; j++) {
                float v = sh[(tn * 4 + j) * 65 + c];
                ull hv = pack2(v, v);
                A[j][0] = fma2(hv, wp0, A[j][0]);
                A[j][1] = fma2(hv, wp1, A[j][1]);
            }
        }
#pragma unroll
        for (int j = 0; j < 4; j++) {
            int n = n0 + tn * 4 + j;
            float2 a0 = unpack2(A[j][0]), a1 = unpack2(A[j][1]);
            __half2* p = (__half2*)&g_hbuf[n * H_DIM + f4];
            p[0] = __floats2half2_rn(a0.x, a0.y);
            p[1] = __floats2half2_rn(a1.x, a1.y);
        }
    }
}

// ---------------- layer-2 CSR gather + bias + relu -> h2buf (fp16) ----------
__global__ void k_gather64(const float* __restrict__ bias) {
    int warp = (blockIdx.x * blockDim.x + threadIdx.x) >> 5;
    int lane = threadIdx.x & 31;
    if (warp >= N_NODES) return;
    int beg = g_off[warp], end = g_off[warp + 1];
    const __half2* __restrict__ src = (const __half2*)g_hbuf;
    float ax = 0.f, ay = 0.f;
    int e = beg;
    for (; e + 3 < end; e += 4) {
        int2 e0 = g_edge[e];
        int2 e1 = g_edge[e + 1];
        int2 e2 = g_edge[e + 2];
        int2 e3 = g_edge[e + 3];
        float2 v0 = __half22float2(src[(size_t)e0.x * 32 + lane]);
        float2 v1 = __half22float2(src[(size_t)e1.x * 32 + lane]);
        float2 v2 = __half22float2(src[(size_t)e2.x * 32 + lane]);
        float2 v3 = __half22float2(src[(size_t)e3.x * 32 + lane]);
        float w0 = __int_as_float(e0.y);
        float w1 = __int_as_float(e1.y);
        float w2 = __int_as_float(e2.y);
        float w3 = __int_as_float(e3.y);
        ax += w0 * v0.x + w1 * v1.x + w2 * v2.x + w3 * v3.x;
        ay += w0 * v0.y + w1 * v1.y + w2 * v2.y + w3 * v3.y;
    }
    for (; e < end; e++) {
        int2 e0 = g_edge[e];
        float2 v0 = __half22float2(src[(size_t)e0.x * 32 + lane]);
        float w0 = __int_as_float(e0.y);
        ax += w0 * v0.x;
        ay += w0 * v0.y;
    }
    float d = g_dinv[warp];
    float2 s = __half22float2(src[(size_t)warp * 32 + lane]);
    ax = d * (ax + d * s.x) + bias[lane * 2];
    ay = d * (ay + d * s.y) + bias[lane * 2 + 1];
    ((__half2*)g_h2buf)[(size_t)warp * 32 + lane] =
        __floats2half2_rn(fmaxf(ax, 0.f), fmaxf(ay, 0.f));
}

// ---------------- conv1: fp16 in/out, f32x2 math, fused BN1 stats -----------
__global__ void k_conv1(const float* __restrict__ w, const float* __restrict__ bias) {
    __shared__ __align__(16) float sw[H_DIM * KW * 36];   // sw[(i*3+k)*36 + o]
    __shared__ float sx[130 * 65];
    __shared__ float s_sum[T_CH], s_sq[T_CH];
    int b = blockIdx.y;
    int t0 = blockIdx.x * 128;
    int t = threadIdx.x;
    if (t < T_CH) { s_sum[t] = 0.f; s_sq[t] = 0.f; }
    for (int j = t; j < T_CH * H_DIM * KW; j += 128) {
        int o = j / (H_DIM * KW), ik = j % (H_DIM * KW);
        sw[ik * 36 + o] = w[j];
    }
    const __half2* __restrict__ hsrc = (const __half2*)g_h2buf;
    for (int j = t; j < 130 * 32; j += 128) {
        int row = j >> 5, cp = j & 31;
        int l = t0 + row - 2;
        float2 v = make_float2(0.f, 0.f);
        if (l >= 0 && l < L_SEQ)
            v = __half22float2(hsrc[((size_t)((b << 12) + l)) * 32 + cp]);
        sx[row * 65 + 2 * cp] = v.x;
        sx[row * 65 + 2 * cp + 1] = v.y;
    }
    __syncthreads();
    int to = t & 7, tq = t >> 3;
    int o4 = to * 4;
    ull A[8][2];
    ull bi0 = pack2(bias[o4], bias[o4 + 1]);
    ull bi1 = pack2(bias[o4 + 2], bias[o4 + 3]);
#pragma unroll
    for (int j = 0; j < 8; j++) { A[j][0] = bi0; A[j][1] = bi1; }
#pragma unroll 4
    for (int i = 0; i < H_DIM; i++) {
        ull xd[10];
#pragma unroll
        for (int r = 0; r < 10; r++) {
            float v = sx[(8 * tq + r) * 65 + i];
            xd[r] = pack2(v, v);
        }
#pragma unroll
        for (int k = 0; k < KW; k++) {
            ulonglong2 wv = *(const ulonglong2*)&sw[(i * 3 + k) * 36 + o4];
#pragma unroll
            for (int j = 0; j < 8; j++) {
                A[j][0] = fma2(xd[j + k], wv.x, A[j][0]);
                A[j][1] = fma2(xd[j + k], wv.y, A[j][1]);
            }
        }
    }
    float acc[8][4];
#pragma unroll
    for (int j = 0; j < 8; j++) {
        float2 a0 = unpack2(A[j][0]), a1 = unpack2(A[j][1]);
        acc[j][0] = a0.x; acc[j][1] = a0.y; acc[j][2] = a1.x; acc[j][3] = a1.y;
    }
    int tb = t0 + 8 * tq;
    float cs[4] = {0.f, 0.f, 0.f, 0.f}, cq[4] = {0.f, 0.f, 0.f, 0.f};
    if (tb + 7 < L1_OUT) {
#pragma unroll
        for (int c = 0; c < 4; c++) {
            __half* p = &g_y1[(b * T_CH + o4 + c) * L1_OUT + tb];
#pragma unroll
            for (int j = 0; j < 4; j++)
                ((__half2*)p)[j] = __floats2half2_rn(acc[2 * j][c], acc[2 * j + 1][c]);
#pragma unroll
            for (int j = 0; j < 8; j++) { cs[c] += acc[j][c]; cq[c] += acc[j][c] * acc[j][c]; }
        }
    } else {
#pragma unroll
        for (int c = 0; c < 4; c++) {
            __half* p = &g_y1[(b * T_CH + o4 + c) * L1_OUT + tb];
#pragma unroll
            for (int j = 0; j < 8; j++)
                if (tb + j < L1_OUT) {
                    p[j] = __float2half(acc[j][c]);
                    cs[c] += acc[j][c]; cq[c] += acc[j][c] * acc[j][c];
                }
        }
    }
#pragma unroll
    for (int c = 0; c < 4; c++) {
        atomicAdd(&s_sum[o4 + c], cs[c]);
        atomicAdd(&s_sq[o4 + c], cq[c]);
    }
    __syncthreads();
    if (t < T_CH) {
        atomicAdd(&g_dstats[t], (double)s_sum[t]);
        atomicAdd(&g_dstats[32 + t], (double)s_sq[t]);
    }
}

// ---------------- conv2: BN1 inline, fp16 in/out, fused BN2 stats -----------
__global__ void k_conv2(const float* __restrict__ w, const float* __restrict__ bias,
                        const float* __restrict__ g1, const float* __restrict__ be1) {
    __shared__ __align__(16) float sw[T_CH * KW * 36];
    __shared__ float sx[130 * 33];
    __shared__ float s_ga[T_CH], s_bb[T_CH];
    __shared__ float s_sum[T_CH], s_sq[T_CH];
    int b = blockIdx.y;
    int t0 = blockIdx.x * 128;
    int t = threadIdx.x;
    if (t < T_CH) {
        double n = (double)B_SZ * L1_OUT;
        double m = g_dstats[t] / n;
        double var = g_dstats[32 + t] / n - m * m;
        float rs = (float)rsqrt(var + EPSF);
        float ga = g1[t] * rs;
        s_ga[t] = ga;
        s_bb[t] = be1[t] - (float)m * ga;
        s_sum[t] = 0.f; s_sq[t] = 0.f;
    }
    for (int j = t; j < T_CH * T_CH * KW; j += 128) {
        int o = j / (T_CH * KW), ik = j % (T_CH * KW);
        sw[ik * 36 + o] = w[j];
    }
    __syncthreads();
    for (int j = t; j < 32 * 130; j += 128) {
        int i = j / 130, row = j % 130;
        int l = t0 + row - 2;
        float v = 0.f;
        if (l >= 0 && l < L1_OUT)
            v = fmaxf(__half2float(g_y1[(b * T_CH + i) * L1_OUT + l]) * s_ga[i] + s_bb[i], 0.f);
        sx[row * 33 + i] = v;
    }
    __syncthreads();
    int to = t & 7, tq = t >> 3;
    int o4 = to * 4;
    ull A[8][2];
    ull bi0 = pack2(bias[o4], bias[o4 + 1]);
    ull bi1 = pack2(bias[o4 + 2], bias[o4 + 3]);
#pragma unroll
    for (int j = 0; j < 8; j++) { A[j][0] = bi0; A[j][1] = bi1; }
#pragma unroll 4
    for (int i = 0; i < T_CH; i++) {
        ull xd[10];
#pragma unroll
        for (int r = 0; r < 10; r++) {
            float v = sx[(8 * tq + r) * 33 + i];
            xd[r] = pack2(v, v);
        }
#pragma unroll
        for (int k = 0; k < KW; k++) {
            ulonglong2 wv = *(const ulonglong2*)&sw[(i * 3 + k) * 36 + o4];
#pragma unroll
            for (int j = 0; j < 8; j++) {
                A[j][0] = fma2(xd[j + k], wv.x, A[j][0]);
                A[j][1] = fma2(xd[j + k], wv.y, A[j][1]);
            }
        }
    }
    float acc[8][4];
#pragma unroll
    for (int j = 0; j < 8; j++) {
        float2 a0 = unpack2(A[j][0]), a1 = unpack2(A[j][1]);
        acc[j][0] = a0.x; acc[j][1] = a0.y; acc[j][2] = a1.x; acc[j][3] = a1.y;
    }
    int tb = t0 + 8 * tq;
    float cs[4] = {0.f, 0.f, 0.f, 0.f}, cq[4] = {0.f, 0.f, 0.f, 0.f};
    if (tb + 7 < L2_OUT) {
#pragma unroll
        for (int c = 0; c < 4; c++) {
            __half* p = &g_y2[(b * T_CH + o4 + c) * L2_OUT + tb];
#pragma unroll
            for (int j = 0; j < 4; j++)
                ((__half2*)p)[j] = __floats2half2_rn(acc[2 * j][c], acc[2 * j + 1][c]);
#pragma unroll
            for (int j = 0; j < 8; j++) { cs[c] += acc[j][c]; cq[c] += acc[j][c] * acc[j][c]; }
        }
    } else {
#pragma unroll
        for (int c = 0; c < 4; c++) {
            __half* p = &g_y2[(b * T_CH + o4 + c) * L2_OUT + tb];
#pragma unroll
            for (int j = 0; j < 8; j++)
                if (tb + j < L2_OUT) {
                    p[j] = __float2half(acc[j][c]);
                    cs[c] += acc[j][c]; cq[c] += acc[j][c] * acc[j][c];
                }
        }
    }
#pragma unroll
    for (int c = 0; c < 4; c++) {
        atomicAdd(&s_sum[o4 + c], cs[c]);
        atomicAdd(&s_sq[o4 + c], cq[c]);
    }
    __syncthreads();
    if (t < T_CH) {
        atomicAdd(&g_dstats[64 + t], (double)s_sum[t]);
        atomicAdd(&g_dstats[96 + t], (double)s_sq[t]);
    }
}

// ---------------- BN2 + relu + mean pool, last block runs FC head ----------
__global__ void k_pool_fc(const float* __restrict__ g2, const float* __restrict__ be2,
                          const float* __restrict__ fc1_w, const float* __restrict__ fc1_b,
                          const float* __restrict__ fc2_w, const float* __restrict__ fc2_b,
                          float* __restrict__ out) {
    int b = blockIdx.x >> 5, o = blockIdx.x & 31;
    double n = (double)B_SZ * L2_OUT;
    double md = g_dstats[64 + o] / n;
    double var = g_dstats[96 + o] / n - md * md;
    float rs = (float)rsqrt(var + EPSF);
    float ga = g2[o] * rs;
    float bb = be2[o] - (float)md * ga;
    const __half* y = g_y2 + (b * T_CH + o) * L2_OUT;
    float s = 0.f;
    for (int i = threadIdx.x; i < L2_OUT; i += 256)
        s += fmaxf(__half2float(y[i]) * ga + bb, 0.f);
    __shared__ float sm[256];
    sm[threadIdx.x] = s;
    __syncthreads();
    for (int st = 128; st > 0; st >>= 1) {
        if (threadIdx.x < st) sm[threadIdx.x] += sm[threadIdx.x + st];
        __syncthreads();
    }
    __shared__ bool last;
    if (threadIdx.x == 0) {
        g_pool[b * T_CH + o] = sm[0] / (float)L2_OUT;
        __threadfence();
        int d = atomicAdd(&g_done, 1);
        last = (d == B_SZ * T_CH - 1);
    }
    __syncthreads();
    if (!last) return;

    __threadfence();
    __shared__ float z[B_SZ * H_DIM];
    int t = threadIdx.x;
    for (int i = t; i < B_SZ * H_DIM; i += 256) {
        int bb2 = i >> 6, j = i & 63;
        float acc = fc1_b[j];
#pragma unroll
        for (int c = 0; c < T_CH; c++)
            acc += __ldcg(&g_pool[bb2 * T_CH + c]) * fc1_w[c * H_DIM + j];
        z[i] = fmaxf(acc, 0.f);
    }
    __syncthreads();
    for (int i = t; i < B_SZ * NCLS; i += 256) {
        int bb2 = i / NCLS, c = i % NCLS;
        float acc = fc2_b[c];
#pragma unroll
        for (int j = 0; j < H_DIM; j++) acc += z[bb2 * H_DIM + j] * fc2_w[j * NCLS + c];
        out[i] = acc;
    }
}

// ---------------- launcher ----------------
extern "C" void kernel_launch(void* const* d_in, const int* in_sizes, int n_in,
                              void* d_out, int out_size) {
    const float* x      = (const float*)d_in[0];
    const float* ew     = (const float*)d_in[1];
    const float* W1     = (const float*)d_in[2];
    const float* b1     = (const float*)d_in[3];
    const float* W2     = (const float*)d_in[4];
    const float* b2     = (const float*)d_in[5];
    const float* tc1_w  = (const float*)d_in[6];
    const float* tc1_b  = (const float*)d_in[7];
    const float* bn1_g  = (const float*)d_in[8];
    const float* bn1_b  = (const float*)d_in[9];
    const float* tc2_w  = (const float*)d_in[10];
    const float* tc2_b  = (const float*)d_in[11];
    const float* bn2_g  = (const float*)d_in[12];
    const float* bn2_b  = (const float*)d_in[13];
    const float* fc1_w  = (const float*)d_in[14];
    const float* fc1_b  = (const float*)d_in[15];
    const float* fc2_w  = (const float*)d_in[16];
    const float* fc2_b  = (const float*)d_in[17];
    const int*   ei     = (const int*)d_in[18];
    float* out = (float*)d_out;

    void* pack_ptr = nullptr;
    cudaGetSymbolAddress(&pack_ptr, g_pack);
    cudaMemsetAsync(pack_ptr, 0, N_NODES * sizeof(ull));

    // CSR build: histogram (+ x->fp16 convert), then fused scan+place
    k_deg_hist<<<N_EDGES / 256, 256>>>(ei, ew, x);
    k_scanplace<<<256, 256>>>(ei, ew);

    // GCN layer 1 + layer-2 transform fused: gather, then gemm1+gemm2
    k_gather22<<<N_NODES * 32 / 256, 256>>>();
    k_gemm12<<<N_NODES / 64, 256>>>(W1, b1, W2);

    // GCN layer 2 aggregation (+bias+relu, fp16 out)
    k_gather64<<<N_NODES * 32 / 256, 256>>>(b2);

    // temporal convs with fused BN stats (fp16 activations, fp32 math)
    k_conv1<<<dim3((L1_OUT + 127) / 128, B_SZ), 128>>>(tc1_w, tc1_b);
    k_conv2<<<dim3((L2_OUT + 127) / 128, B_SZ), 128>>>(tc2_w, tc2_b, bn1_g, bn1_b);

    // BN2 + relu + pool + FC head (fused)
    k_pool_fc<<<B_SZ * T_CH, 256>>>(bn2_g, bn2_b, fc1_w, fc1_b, fc2_w, fc2_b, out);
}